// round 14
// baseline (speedup 1.0000x reference)
#include <cuda_runtime.h>
#include <cuda_fp16.h>

#define B        64
#define NV       100000
#define NE       (3 * NV)        // 300000 floats per batch row
#define NT       200000          // tets
#define VOL_BLOCKS 1184          // 8 blocks/SM * 148 SMs
#define E_TILE   64
#define T_TILES  ((NE + E_TILE - 1) / E_TILE)   // 4688 (last tile: 32 rows)
#define P_BLOCKS ((NT + 255) / 256)             // 782 prep blocks
#define S_TILES  ((NE + 63) / 64)               // 4688 scale tiles

// Scratch (static device globals — no runtime allocation)
__device__ __half    g_xt[B * NE];               // transposed fp16: xt[e*64 + b]
__device__ int4      g_off4[NT];                 // {o0,o1,o2,pad}, o = idx*192
__device__ float     g_part[B * VOL_BLOCKS];     // partials, [b][blk] transposed
__device__ float     g_inv[B];                   // 1/cbrt(vol)
__device__ unsigned  g_count = 0;                // last-block counter (self-resetting)

// ---------------------------------------------------------------------------
// Kernel 0 (heterogeneous): blocks [0, T_TILES) transpose+convert x -> xt
// ([b][e] tile, stride 68: LDG.128 -> STS.128, scalar LDS -> STG.128);
// blocks [T_TILES, ...) convert M -> fused int4 offsets.
// ---------------------------------------------------------------------------
__global__ void k_pt(const float* __restrict__ x, const void* __restrict__ Mv) {
    __shared__ float tile[64][68];            // [b][e_local], 16B-aligned rows
    const int tid = threadIdx.x;              // 256 threads

    if (blockIdx.x < T_TILES) {
        const int e0 = blockIdx.x * E_TILE;
        // load: 1024 tasks = 64 b x 16 float4-chunks along e; STS.128
        #pragma unroll
        for (int k = 0; k < 4; k++) {
            int task = tid + k * 256;
            int b  = task >> 4;               // 0..63
            int c4 = task & 15;               // float4 chunk along e
            int e  = e0 + 4 * c4;
            if (e < NE) {
                float4 v = __ldcs((const float4*)(x + b * NE + e));
                *(float4*)&tile[b][4 * c4] = v;
            }
        }
        __syncthreads();
        // store: 512 tasks = 64 e x 8 chunks of 8 halves along b
        #pragma unroll
        for (int k = 0; k < 2; k++) {
            int task = tid + k * 256;
            int e = task >> 3;                // 0..63
            int c = task & 7;                 // 8-half chunk along b
            if (e0 + e < NE) {
                __half2 h[4];
                #pragma unroll
                for (int j = 0; j < 4; j++)
                    h[j] = __floats2half2_rn(tile[8 * c + 2 * j][e],
                                             tile[8 * c + 2 * j + 1][e]);
                ((int4*)(g_xt + (e0 + e) * B))[c] = *(int4*)h;
            }
        }
    } else {
        // ---------------- index-prep path ----------------
        __shared__ int s_is64;
        if (tid == 0) {
            const int* Mi = (const int*)Mv;
            int nz = 0;
            #pragma unroll
            for (int k = 0; k < 32; k++) nz |= Mi[2 * k + 1];
            s_is64 = (nz == 0);
        }
        __syncthreads();
        int t = (blockIdx.x - T_TILES) * 256 + tid;
        if (t >= NT) return;
        int i0, i1, i2;
        if (s_is64) {
            const long long* Ml = (const long long*)Mv;
            i0 = (int)Ml[3 * t]; i1 = (int)Ml[3 * t + 1]; i2 = (int)Ml[3 * t + 2];
        } else {
            const int* Mi = (const int*)Mv;
            i0 = Mi[3 * t]; i1 = Mi[3 * t + 1]; i2 = Mi[3 * t + 2];
        }
        g_off4[t] = make_int4(i0 * (3 * B), i1 * (3 * B), i2 * (3 * B), 0);
    }
}

// ---------------------------------------------------------------------------
// Kernel 1: per-batch |det| partial sums + fused last-block reduce.
// Block = 256 threads = 32 lanes (half2 = 2 batches) x 8 tet-streams.
// det math in half2, fp32 accumulation. (Proven R12 structure.)
// ---------------------------------------------------------------------------
__global__ void k_volume() {
    const int tid  = threadIdx.x;
    const int lane = tid & 31;                // batch-pair id
    const int sub  = tid >> 5;                // tet stream 0..7

    float2 acc = make_float2(0.0f, 0.0f);
    const int stride = VOL_BLOCKS * 8;
    #pragma unroll 4
    for (int t = blockIdx.x * 8 + sub; t < NT; t += stride) {
        const int4 o = __ldg(&g_off4[t]);

        const __half2* p0 = (const __half2*)(g_xt + o.x) + lane;
        const __half2* p1 = (const __half2*)(g_xt + o.y) + lane;
        const __half2* p2 = (const __half2*)(g_xt + o.z) + lane;

        __half2 ax = p0[0], ay = p0[32], az = p0[64];
        __half2 bx = p1[0], by = p1[32], bz = p1[64];
        __half2 cx = p2[0], cy = p2[32], cz = p2[64];

        __half2 nbz = __hneg2(bz);
        __half2 m0 = __hfma2(by, cz, __hmul2(nbz, cy));         // by*cz - bz*cy
        __half2 m1 = __hfma2(bx, cz, __hmul2(nbz, cx));         // bx*cz - bz*cx
        __half2 m2 = __hfma2(bx, cy, __hmul2(__hneg2(by), cx)); // bx*cy - by*cx

        __half2 det = __hmul2(ax, m0);
        det = __hfma2(__hneg2(ay), m1, det);
        det = __hfma2(az, m2, det);
        det = __habs2(det);

        float2 f = __half22float2(det);
        acc.x += f.x;
        acc.y += f.y;
    }

    __shared__ float2 sred[8][32];
    sred[sub][lane] = acc;
    __syncthreads();
    if (sub == 0) {
        float2 s = acc;
        #pragma unroll
        for (int r = 1; r < 8; r++) {
            s.x += sred[r][lane].x;
            s.y += sred[r][lane].y;
        }
        g_part[(2 * lane + 0) * VOL_BLOCKS + blockIdx.x] = s.x;
        g_part[(2 * lane + 1) * VOL_BLOCKS + blockIdx.x] = s.y;
    }

    // ---- fused deterministic reduce in the last block to finish ----
    __shared__ int s_last;
    if (tid == 0) {
        __threadfence();
        unsigned c = atomicAdd(&g_count, 1u);
        s_last = (c == VOL_BLOCKS - 1);
    }
    __syncthreads();
    if (!s_last) return;

    {
        const int b = tid >> 2;               // 0..63
        const int q = tid & 3;                // 296-float contiguous chunk
        const float4* p = (const float4*)(g_part + b * VOL_BLOCKS + q * 296);
        float s = 0.0f;
        #pragma unroll 4
        for (int i = 0; i < 74; i++) {
            float4 v = p[i];
            s += (v.x + v.y) + (v.z + v.w);
        }
        __shared__ float sq[64][4];
        sq[b][q] = s;
        __syncthreads();
        if (tid < 64) {
            float vol = ((sq[tid][0] + sq[tid][1]) + (sq[tid][2] + sq[tid][3]))
                        * (1.0f / 6.0f);
            g_inv[tid] = 1.0f / cbrtf(vol);
        }
        if (tid == 0) g_count = 0;            // reset for next graph replay
    }
}

// ---------------------------------------------------------------------------
// Kernel 2: out[b][e] = float(xt[e][b]) * g_inv[b].
// [b][e] tile, stride 68: coalesced int4 xt reads (L2-hot after k_volume),
// scalar STS scatter, LDS.128 + STG.128 streaming writes.
// ---------------------------------------------------------------------------
__global__ void k_scale(float* __restrict__ out) {
    __shared__ float ssc[64];
    __shared__ float tile[64][68];            // [b][e_local]
    const int tid = threadIdx.x;              // 256 threads
    const int e0 = blockIdx.x * 64;

    if (tid < 64) ssc[tid] = g_inv[tid];
    __syncthreads();

    // load+scale: 512 tasks = 64 e-rows x 8 int4-chunks (8 halves along b)
    #pragma unroll
    for (int k = 0; k < 2; k++) {
        int task = tid + k * 256;
        int e = task >> 3;                    // 0..63
        int c = task & 7;
        if (e0 + e < NE) {
            int4 raw = __ldg(&((const int4*)(g_xt + (e0 + e) * B))[c]);
            __half2* h = (__half2*)&raw;
            #pragma unroll
            for (int j = 0; j < 4; j++) {
                float2 f = __half22float2(h[j]);
                tile[8 * c + 2 * j][e]     = f.x * ssc[8 * c + 2 * j];
                tile[8 * c + 2 * j + 1][e] = f.y * ssc[8 * c + 2 * j + 1];
            }
        }
    }
    __syncthreads();

    // write: 1024 tasks = 64 b-rows x 16 float4 along e (LDS.128 aligned)
    #pragma unroll
    for (int k = 0; k < 4; k++) {
        int task = tid + k * 256;
        int b = task >> 4;                    // 0..63
        int q = task & 15;
        int e = e0 + 4 * q;
        if (e < NE) {
            float4 v = *(float4*)&tile[b][4 * q];
            __stcs((float4*)(out + b * NE + e), v);
        }
    }
}

// ---------------------------------------------------------------------------
extern "C" void kernel_launch(void* const* d_in, const int* in_sizes, int n_in,
                              void* d_out, int out_size) {
    const float* x = (const float*)d_in[0];
    const void*  M = d_in[1];
    float*     out = (float*)d_out;

    k_pt<<<T_TILES + P_BLOCKS, 256>>>(x, M);
    k_volume<<<VOL_BLOCKS, 256>>>();
    k_scale<<<S_TILES, 256>>>(out);
}

// round 15
// speedup vs baseline: 1.2634x; 1.2634x over previous
#include <cuda_runtime.h>
#include <cuda_fp16.h>

#define B        64
#define NV       100000
#define NE       (3 * NV)        // 300000 floats per batch row
#define NT       200000          // tets
#define VOL_BLOCKS 1184          // 8 blocks/SM * 148 SMs
#define E_TILE   64
#define T_TILES  ((NE + E_TILE - 1) / E_TILE)   // 4688 (last tile: 32 rows)
#define P_BLOCKS ((NT + 255) / 256)             // 782 prep blocks
#define S_TILES  ((NE + 63) / 64)               // 4688 scale tiles

// Scratch (static device globals — no runtime allocation)
__device__ __half    g_xt[B * NE];               // transposed fp16: xt[e*64 + b]
__device__ int4      g_off4[NT];                 // {o0,o1,o2,pad}, o = idx*192
__device__ float     g_part[B * VOL_BLOCKS];     // partials, [b][blk] transposed
__device__ float     g_inv[B];                   // 1/cbrt(vol)
__device__ unsigned  g_count = 0;                // last-block counter (self-resetting)

// ---------------------------------------------------------------------------
// Kernel 0 (heterogeneous): blocks [0, T_TILES) transpose+convert x -> xt.
// Tile stored as flat float4 chunks, chunk = b*16 + (c4 ^ (b>>3)):
//   load phase:    LDG.128 -> one STS.128 (swizzled chunk)
//   convert phase: scalar LDS column reads, banks 4*((e>>2)^(b>>3))+(e&3)
//                  -> all 32 lanes distinct (conflict-free), then STG.128.
// Blocks [T_TILES, ...) convert M -> fused int4 offsets.
// ---------------------------------------------------------------------------
__global__ void k_pt(const float* __restrict__ x, const void* __restrict__ Mv) {
    __shared__ float4 sf4[64 * 16];           // 16 KB, no padding (swizzled)
    const int tid = threadIdx.x;              // 256 threads

    if (blockIdx.x < T_TILES) {
        const int e0 = blockIdx.x * E_TILE;
        // load: 1024 tasks = 64 b x 16 float4-chunks along e
        #pragma unroll
        for (int k = 0; k < 4; k++) {
            int task = tid + k * 256;
            int b  = task >> 4;               // 0..63
            int c4 = task & 15;               // float4 chunk along e
            int e  = e0 + 4 * c4;
            if (e < NE) {
                float4 v = __ldcs((const float4*)(x + b * NE + e));
                sf4[b * 16 + (c4 ^ (b >> 3))] = v;
            }
        }
        __syncthreads();
        // convert: 512 tasks = 64 e x 8 chunks of 8 halves along b
        const float* sf = (const float*)sf4;
        #pragma unroll
        for (int k = 0; k < 2; k++) {
            int task = tid + k * 256;
            int e = task >> 3;                // 0..63
            int c = task & 7;                 // 8-half chunk along b
            if (e0 + e < NE) {
                const int eq = e >> 2, er = e & 3;
                __half2 h[4];
                #pragma unroll
                for (int j = 0; j < 4; j++) {
                    int b0 = 8 * c + 2 * j;
                    int b1 = b0 + 1;
                    float f0 = sf[(b0 * 16 + (eq ^ (b0 >> 3))) * 4 + er];
                    float f1 = sf[(b1 * 16 + (eq ^ (b1 >> 3))) * 4 + er];
                    h[j] = __floats2half2_rn(f0, f1);
                }
                ((int4*)(g_xt + (e0 + e) * B))[c] = *(int4*)h;
            }
        }
    } else {
        // ---------------- index-prep path ----------------
        __shared__ int s_is64;
        if (tid == 0) {
            const int* Mi = (const int*)Mv;
            int nz = 0;
            #pragma unroll
            for (int k = 0; k < 32; k++) nz |= Mi[2 * k + 1];
            s_is64 = (nz == 0);
        }
        __syncthreads();
        int t = (blockIdx.x - T_TILES) * 256 + tid;
        if (t >= NT) return;
        int i0, i1, i2;
        if (s_is64) {
            const long long* Ml = (const long long*)Mv;
            i0 = (int)Ml[3 * t]; i1 = (int)Ml[3 * t + 1]; i2 = (int)Ml[3 * t + 2];
        } else {
            const int* Mi = (const int*)Mv;
            i0 = Mi[3 * t]; i1 = Mi[3 * t + 1]; i2 = Mi[3 * t + 2];
        }
        g_off4[t] = make_int4(i0 * (3 * B), i1 * (3 * B), i2 * (3 * B), 0);
    }
}

// ---------------------------------------------------------------------------
// Kernel 1: per-batch |det| partial sums + fused last-block reduce.
// Block = 256 threads = 32 lanes (half2 = 2 batches) x 8 tet-streams.
// det math in half2, fp32 accumulation. (Exact proven R12 version.)
// ---------------------------------------------------------------------------
__global__ void k_volume() {
    const int tid  = threadIdx.x;
    const int lane = tid & 31;                // batch-pair id
    const int sub  = tid >> 5;                // tet stream 0..7

    float2 acc = make_float2(0.0f, 0.0f);
    const int stride = VOL_BLOCKS * 8;
    #pragma unroll 4
    for (int t = blockIdx.x * 8 + sub; t < NT; t += stride) {
        const int4 o = __ldg(&g_off4[t]);

        const __half2* p0 = (const __half2*)(g_xt + o.x) + lane;
        const __half2* p1 = (const __half2*)(g_xt + o.y) + lane;
        const __half2* p2 = (const __half2*)(g_xt + o.z) + lane;

        __half2 ax = p0[0], ay = p0[32], az = p0[64];
        __half2 bx = p1[0], by = p1[32], bz = p1[64];
        __half2 cx = p2[0], cy = p2[32], cz = p2[64];

        __half2 nbz = __hneg2(bz);
        __half2 m0 = __hfma2(by, cz, __hmul2(nbz, cy));         // by*cz - bz*cy
        __half2 m1 = __hfma2(bx, cz, __hmul2(nbz, cx));         // bx*cz - bz*cx
        __half2 m2 = __hfma2(bx, cy, __hmul2(__hneg2(by), cx)); // bx*cy - by*cx

        __half2 det = __hmul2(ax, m0);
        det = __hfma2(__hneg2(ay), m1, det);
        det = __hfma2(az, m2, det);
        det = __habs2(det);

        float2 f = __half22float2(det);
        acc.x += f.x;
        acc.y += f.y;
    }

    __shared__ float2 sred[8][32];
    sred[sub][lane] = acc;
    __syncthreads();
    if (sub == 0) {
        float2 s = acc;
        #pragma unroll
        for (int r = 1; r < 8; r++) {
            s.x += sred[r][lane].x;
            s.y += sred[r][lane].y;
        }
        g_part[(2 * lane + 0) * VOL_BLOCKS + blockIdx.x] = s.x;
        g_part[(2 * lane + 1) * VOL_BLOCKS + blockIdx.x] = s.y;
    }

    // ---- fused deterministic reduce in the last block to finish ----
    __shared__ int s_last;
    if (tid == 0) {
        __threadfence();
        unsigned c = atomicAdd(&g_count, 1u);
        s_last = (c == VOL_BLOCKS - 1);
    }
    __syncthreads();
    if (!s_last) return;

    {
        const int b = tid >> 2;               // 0..63
        const int q = tid & 3;                // 296-float contiguous chunk
        const float4* p = (const float4*)(g_part + b * VOL_BLOCKS + q * 296);
        float s = 0.0f;
        #pragma unroll 4
        for (int i = 0; i < 74; i++) {
            float4 v = p[i];
            s += (v.x + v.y) + (v.z + v.w);
        }
        __shared__ float sq[64][4];
        sq[b][q] = s;
        __syncthreads();
        if (tid < 64) {
            float vol = ((sq[tid][0] + sq[tid][1]) + (sq[tid][2] + sq[tid][3]))
                        * (1.0f / 6.0f);
            g_inv[tid] = 1.0f / cbrtf(vol);
        }
        if (tid == 0) g_count = 0;            // reset for next graph replay
    }
}

// ---------------------------------------------------------------------------
// Kernel 2: out[b][e] = float(xt[e][b]) * g_inv[b].
// 64e x 64b tiles: coalesced int4 xt reads (L2-hot after k_volume),
// smem transpose ([b][e] stride 65), float4 writes from scalar LDS.
// (Exact proven R12 version.)
// ---------------------------------------------------------------------------
__global__ void k_scale(float* __restrict__ out) {
    __shared__ float ssc[64];
    __shared__ float tile[64][65];            // [b][e_local]
    const int tid = threadIdx.x;              // 256 threads
    const int e0 = blockIdx.x * 64;

    if (tid < 64) ssc[tid] = g_inv[tid];
    __syncthreads();

    // load+scale: 512 tasks = 64 e-rows x 8 int4-chunks (8 halves along b)
    #pragma unroll
    for (int k = 0; k < 2; k++) {
        int task = tid + k * 256;
        int e = task >> 3;                    // 0..63
        int c = task & 7;
        if (e0 + e < NE) {
            int4 raw = __ldg(&((const int4*)(g_xt + (e0 + e) * B))[c]);
            __half2* h = (__half2*)&raw;
            #pragma unroll
            for (int j = 0; j < 4; j++) {
                float2 f = __half22float2(h[j]);
                tile[8 * c + 2 * j][e]     = f.x * ssc[8 * c + 2 * j];
                tile[8 * c + 2 * j + 1][e] = f.y * ssc[8 * c + 2 * j + 1];
            }
        }
    }
    __syncthreads();

    // write: 1024 tasks = 64 b-rows x 16 float4 along e
    #pragma unroll
    for (int k = 0; k < 4; k++) {
        int task = tid + k * 256;
        int b = task >> 4;                    // 0..63
        int q = task & 15;
        int e = e0 + 4 * q;
        if (e < NE) {
            float4 v = make_float4(tile[b][4 * q + 0], tile[b][4 * q + 1],
                                   tile[b][4 * q + 2], tile[b][4 * q + 3]);
            *(float4*)(out + b * NE + e) = v;
        }
    }
}

// ---------------------------------------------------------------------------
extern "C" void kernel_launch(void* const* d_in, const int* in_sizes, int n_in,
                              void* d_out, int out_size) {
    const float* x = (const float*)d_in[0];
    const void*  M = d_in[1];
    float*     out = (float*)d_out;

    k_pt<<<T_TILES + P_BLOCKS, 256>>>(x, M);
    k_volume<<<VOL_BLOCKS, 256>>>();
    k_scale<<<S_TILES, 256>>>(out);
}